// round 2
// baseline (speedup 1.0000x reference)
#include <cuda_runtime.h>
#include <cuda_fp16.h>

// ---------------- problem constants ----------------
#define NB   64      // batches
#define NT   256     // tokens (MAX_TOKENS)
#define NC   256     // channels
#define HW   4096    // H*W
#define NITER 30

// log2(e)/eps  and its inverse (= eps*ln2)
#define K2C     28.853900817779268f
#define INV_K2  0.03465735902799727f
#define SHIFTF  26.0f
#define MUC     (1.0f/256.0f)

// ---------------- scratch (device globals; no runtime alloc) ----------------
__device__ float  g_tok[(size_t)2 * NB * NT * NC];        // normalized tokens [tensor][b][tok][ch]
__device__ __half g_K[(size_t)NB * NT * NT];              // scaled kernel K' fp16
__device__ float  g_loss[NB];

// ---------------- f32x2 packed helpers ----------------
__device__ __forceinline__ unsigned long long pk2(float lo, float hi) {
    unsigned long long r;
    asm("mov.b64 %0, {%1, %2};" : "=l"(r) : "f"(lo), "f"(hi));
    return r;
}
__device__ __forceinline__ void fma2(unsigned long long& d, unsigned long long a, unsigned long long b) {
    asm("fma.rn.f32x2 %0, %1, %2, %0;" : "+l"(d) : "l"(a), "l"(b));
}
__device__ __forceinline__ float2 up2(unsigned long long v) {
    float lo, hi;
    asm("mov.b64 {%0, %1}, %2;" : "=f"(lo), "=f"(hi) : "l"(v));
    return make_float2(lo, hi);
}

// ============================================================================
// Kernel A: gather linspace-sampled tokens, l2-normalize, write [tok][ch] fp32
// grid (64 batches, 2 tensors), 256 threads
// ============================================================================
__global__ __launch_bounds__(256) void gather_norm_kernel(
    const float* __restrict__ pred, const float* __restrict__ tgt)
{
    const int b = blockIdx.x;
    const int z = blockIdx.y;
    const float* __restrict__ base = (z ? tgt : pred) + (size_t)b * NC * HW;
    float* __restrict__ dst = g_tok + (((size_t)z * NB + b) * NT) * NC;

    const int w    = threadIdx.x >> 5;
    const int lane = threadIdx.x & 31;
    const float DELTA = 4095.0f / 255.0f;   // compile-time IEEE rn division (matches XLA)

    for (int t = 0; t < 32; ++t) {
        const int i = w * 32 + t;                         // token index 0..255
        const int s = (int)(__fmul_rn((float)i, DELTA));  // bit-exact jnp.linspace truncation
        float x[8];
        float ss = 0.0f;
        #pragma unroll
        for (int q = 0; q < 8; ++q) {
            x[q] = __ldg(base + (size_t)(lane * 8 + q) * HW + s);
            ss = fmaf(x[q], x[q], ss);
        }
        #pragma unroll
        for (int o = 16; o; o >>= 1) ss += __shfl_xor_sync(0xffffffffu, ss, o);
        const float inv = __fdividef(1.0f, fmaxf(sqrtf(ss), 1e-12f));
        float4 o0 = make_float4(x[0]*inv, x[1]*inv, x[2]*inv, x[3]*inv);
        float4 o1 = make_float4(x[4]*inv, x[5]*inv, x[6]*inv, x[7]*inv);
        *(float4*)&dst[(size_t)i * NC + lane * 8 + 0] = o0;
        *(float4*)&dst[(size_t)i * NC + lane * 8 + 4] = o1;
    }
}

// ============================================================================
// Kernel B: cost GEMM (fp32, FFMA2) + K' = exp2((dot-1)*K2C + 26) -> fp16
// grid (16 tiles of 64x64, 64 batches), 256 threads, 4x4 outputs/thread
// ============================================================================
__global__ __launch_bounds__(256) void cost_kernel()
{
    __shared__ float As[16][68];
    __shared__ float Bs[16][68];

    const int b  = blockIdx.y;
    const int tm = (blockIdx.x & 3) * 64;
    const int tn = (blockIdx.x >> 2) * 64;

    const float* __restrict__ A = g_tok + ((size_t)b * NT) * NC;              // pred
    const float* __restrict__ B = g_tok + (((size_t)NB + b) * NT) * NC;       // target

    const int t  = threadIdx.x;
    const int tx = t & 15;
    const int ty = t >> 4;
    const int lr = t >> 2;          // 0..63 (tile row to load)
    const int lc = (t & 3) * 4;     // k-offset within chunk

    unsigned long long acc[4][2] = {};

    for (int kc = 0; kc < NC; kc += 16) {
        float4 av = *(const float4*)&A[(size_t)(tm + lr) * NC + kc + lc];
        float4 bv = *(const float4*)&B[(size_t)(tn + lr) * NC + kc + lc];
        __syncthreads();
        As[lc + 0][lr] = av.x; As[lc + 1][lr] = av.y; As[lc + 2][lr] = av.z; As[lc + 3][lr] = av.w;
        Bs[lc + 0][lr] = bv.x; Bs[lc + 1][lr] = bv.y; Bs[lc + 2][lr] = bv.z; Bs[lc + 3][lr] = bv.w;
        __syncthreads();

        #pragma unroll
        for (int k = 0; k < 16; ++k) {
            const float4 a  = *(const float4*)&As[k][ty * 4];
            const float4 bq = *(const float4*)&Bs[k][tx * 4];
            const unsigned long long b01 = pk2(bq.x, bq.y);
            const unsigned long long b23 = pk2(bq.z, bq.w);
            unsigned long long ar;
            ar = pk2(a.x, a.x); fma2(acc[0][0], ar, b01); fma2(acc[0][1], ar, b23);
            ar = pk2(a.y, a.y); fma2(acc[1][0], ar, b01); fma2(acc[1][1], ar, b23);
            ar = pk2(a.z, a.z); fma2(acc[2][0], ar, b01); fma2(acc[2][1], ar, b23);
            ar = pk2(a.w, a.w); fma2(acc[3][0], ar, b01); fma2(acc[3][1], ar, b23);
        }
    }

    __half* __restrict__ Kout = g_K + (size_t)b * NT * NT;
    #pragma unroll
    for (int r = 0; r < 4; ++r) {
        const float2 c01 = up2(acc[r][0]);
        const float2 c23 = up2(acc[r][1]);
        const int m = tm + ty * 4 + r;
        const int n = tn + tx * 4;
        __half2* p = (__half2*)(Kout + (size_t)m * NT + n);
        p[0] = __halves2half2(__float2half_rn(exp2f(fmaf(c01.x - 1.0f, K2C, SHIFTF))),
                              __float2half_rn(exp2f(fmaf(c01.y - 1.0f, K2C, SHIFTF))));
        p[1] = __halves2half2(__float2half_rn(exp2f(fmaf(c23.x - 1.0f, K2C, SHIFTF))),
                              __float2half_rn(exp2f(fmaf(c23.y - 1.0f, K2C, SHIFTF))));
    }
}

// ============================================================================
// Kernel C: linear-domain Sinkhorn (30 iters) + transport loss. 1 CTA / batch.
// K' in smem fp16 (128KB). 1024 threads.
// ============================================================================
#define SINK_SMEM (131072 + 1024 + 1024 + 16384 + 128)

__global__ __launch_bounds__(1024, 1) void sinkhorn_kernel()
{
    extern __shared__ unsigned char sm[];
    __half* Ks  = (__half*)sm;                               // [256][256] fp16
    float*  u   = (float*)(sm + 131072);                     // [256]
    float*  v   = (float*)(sm + 131072 + 1024);              // [256]
    float*  prt = (float*)(sm + 131072 + 2048);              // [16][256]
    float*  red = (float*)(sm + 131072 + 2048 + 16384);      // [32]

    const int b    = blockIdx.x;
    const int tid  = threadIdx.x;
    const int w    = tid >> 5;
    const int lane = tid & 31;

    // load K' (128KB) via uint4
    {
        const uint4* gk = (const uint4*)(g_K + (size_t)b * NT * NT);
        uint4* sk = (uint4*)Ks;
        #pragma unroll
        for (int q = 0; q < 8; ++q) sk[tid + q * 1024] = gk[tid + q * 1024];
    }
    if (tid < NT) v[tid] = 1.0f;
    __syncthreads();

    const int jq = tid & 63;   // column quad (cols 4*jq .. +3)
    const int g  = tid >> 6;   // row group (16 rows)

    for (int it = 0; it < NITER; ++it) {
        // ---- u-pass: warp w handles rows 8w..8w+7; lane owns channels lane*8..+7
        const float4 v0 = *(const float4*)&v[lane * 8];
        const float4 v1 = *(const float4*)&v[lane * 8 + 4];
        const unsigned long long vv0 = pk2(v0.x, v0.y), vv1 = pk2(v0.z, v0.w);
        const unsigned long long vv2 = pk2(v1.x, v1.y), vv3 = pk2(v1.z, v1.w);
        #pragma unroll
        for (int r = 0; r < 8; ++r) {
            const int i = w * 8 + r;
            const uint4 kw = *(const uint4*)(Ks + (size_t)i * NT + lane * 8);
            unsigned long long a0 = 0ull, a1 = 0ull;
            float2 f;
            f = __half22float2(*(const __half2*)&kw.x); fma2(a0, pk2(f.x, f.y), vv0);
            f = __half22float2(*(const __half2*)&kw.y); fma2(a1, pk2(f.x, f.y), vv1);
            f = __half22float2(*(const __half2*)&kw.z); fma2(a0, pk2(f.x, f.y), vv2);
            f = __half22float2(*(const __half2*)&kw.w); fma2(a1, pk2(f.x, f.y), vv3);
            const float2 s0 = up2(a0), s1 = up2(a1);
            float s = (s0.x + s0.y) + (s1.x + s1.y);
            #pragma unroll
            for (int o = 16; o; o >>= 1) s += __shfl_xor_sync(0xffffffffu, s, o);
            if (lane == 0) u[i] = __fdividef(MUC, s);
        }
        __syncthreads();

        // ---- v-pass: thread accumulates 4 columns over its 16 rows
        float a0 = 0.f, a1 = 0.f, a2 = 0.f, a3 = 0.f;
        #pragma unroll
        for (int r = 0; r < 16; ++r) {
            const int i = g * 16 + r;
            const float ui = u[i];
            const uint2 kw = *(const uint2*)(Ks + (size_t)i * NT + jq * 4);
            const float2 f0 = __half22float2(*(const __half2*)&kw.x);
            const float2 f1 = __half22float2(*(const __half2*)&kw.y);
            a0 = fmaf(f0.x, ui, a0); a1 = fmaf(f0.y, ui, a1);
            a2 = fmaf(f1.x, ui, a2); a3 = fmaf(f1.y, ui, a3);
        }
        *(float4*)&prt[g * NT + jq * 4] = make_float4(a0, a1, a2, a3);
        __syncthreads();
        if (tid < NT) {
            float s = 0.f;
            #pragma unroll
            for (int gg = 0; gg < 16; ++gg) s += prt[gg * NT + tid];
            v[tid] = __fdividef(MUC, s);
        }
        __syncthreads();
    }

    // ---- transport loss: sum_ij u_i K'_ij v_j * cost_ij, cost from log2(K')
    float vl[8];
    {
        const float4 v0 = *(const float4*)&v[lane * 8];
        const float4 v1 = *(const float4*)&v[lane * 8 + 4];
        vl[0]=v0.x; vl[1]=v0.y; vl[2]=v0.z; vl[3]=v0.w;
        vl[4]=v1.x; vl[5]=v1.y; vl[6]=v1.z; vl[7]=v1.w;
    }
    float acc = 0.0f;
    #pragma unroll
    for (int r = 0; r < 8; ++r) {
        const int i = w * 8 + r;
        const float ui = u[i];
        const uint4 kw = *(const uint4*)(Ks + (size_t)i * NT + lane * 8);
        float kf[8];
        {
            float2 f;
            f = __half22float2(*(const __half2*)&kw.x); kf[0]=f.x; kf[1]=f.y;
            f = __half22float2(*(const __half2*)&kw.y); kf[2]=f.x; kf[3]=f.y;
            f = __half22float2(*(const __half2*)&kw.z); kf[4]=f.x; kf[5]=f.y;
            f = __half22float2(*(const __half2*)&kw.w); kf[6]=f.x; kf[7]=f.y;
        }
        #pragma unroll
        for (int q = 0; q < 8; ++q) {
            const float k = kf[q];
            if (k > 0.0f) {
                const float cost = (SHIFTF - __log2f(k)) * INV_K2;  // == 1 - dot
                acc = fmaf(ui * k * vl[q], cost, acc);
            }
        }
    }
    #pragma unroll
    for (int o = 16; o; o >>= 1) acc += __shfl_xor_sync(0xffffffffu, acc, o);
    if (lane == 0) red[w] = acc;
    __syncthreads();
    if (w == 0) {
        float s = red[lane];
        #pragma unroll
        for (int o = 16; o; o >>= 1) s += __shfl_xor_sync(0xffffffffu, s, o);
        if (lane == 0) g_loss[b] = s;
    }
}

// ============================================================================
// Kernel D: deterministic mean over 64 per-batch losses
// ============================================================================
__global__ void finalize_kernel(float* __restrict__ out)
{
    if (threadIdx.x == 0) {
        float s = 0.0f;
        #pragma unroll
        for (int i = 0; i < NB; ++i) s += g_loss[i];
        out[0] = s * (1.0f / NB);
    }
}

// ============================================================================
extern "C" void kernel_launch(void* const* d_in, const int* in_sizes, int n_in,
                              void* d_out, int out_size)
{
    const float* pred = (const float*)d_in[0];
    const float* tgt  = (const float*)d_in[1];
    float* out = (float*)d_out;

    gather_norm_kernel<<<dim3(NB, 2), 256>>>(pred, tgt);
    cost_kernel<<<dim3(16, NB), 256>>>();
    cudaFuncSetAttribute(sinkhorn_kernel, cudaFuncAttributeMaxDynamicSharedMemorySize, SINK_SMEM);
    sinkhorn_kernel<<<NB, 1024, SINK_SMEM>>>();
    finalize_kernel<<<1, 32>>>(out);
}

// round 4
// speedup vs baseline: 1.1542x; 1.1542x over previous
#include <cuda_runtime.h>
#include <cuda_fp16.h>
#include <cuda_bf16.h>
#include <cstdint>

// ---------------- problem constants ----------------
#define NB   64
#define NT   256
#define NC   256
#define HW   4096
#define NITER 30

#define K2C     28.853900817779268f   // log2(e)/eps
#define INV_K2  0.03465735902799727f  // eps*ln2
#define SHIFTF  26.0f
#define MUC     (1.0f/256.0f)

// ---------------- scratch ----------------
__device__ __align__(16) __nv_bfloat16 g_tok[(size_t)2 * NB * NT * NC];
__device__ __align__(16) __half        g_K[(size_t)NB * NT * NT];
__device__ float    g_loss[NB];
__device__ unsigned g_ctr;

// ============================================================================
// Kernel A: gather + l2norm -> bf16 tokens.  grid (64, 2, 8), 256 threads.
// One warp handles 4 tokens; all 32 LDGs front-batched for max MLP.
// ============================================================================
__global__ __launch_bounds__(256) void gather_norm_kernel(
    const float* __restrict__ pred, const float* __restrict__ tgt)
{
    if ((blockIdx.x | blockIdx.y | blockIdx.z) == 0 && threadIdx.x == 0) g_ctr = 0u;

    const int b = blockIdx.x, z = blockIdx.y;
    const float* __restrict__ base = (z ? tgt : pred) + (size_t)b * NC * HW;
    __nv_bfloat16* __restrict__ dst = g_tok + (((size_t)z * NB + b) * NT) * NC;

    const int w = threadIdx.x >> 5, lane = threadIdx.x & 31;
    const float DELTA = 4095.0f / 255.0f;
    const int i0 = (blockIdx.z * 8 + w) * 4;

    float x[4][8];
    #pragma unroll
    for (int t = 0; t < 4; ++t) {
        const int s = (int)(__fmul_rn((float)(i0 + t), DELTA));  // bit-exact linspace trunc
        #pragma unroll
        for (int q = 0; q < 8; ++q)
            x[t][q] = __ldg(base + (size_t)(lane * 8 + q) * HW + s);
    }
    #pragma unroll
    for (int t = 0; t < 4; ++t) {
        float ss = 0.0f;
        #pragma unroll
        for (int q = 0; q < 8; ++q) ss = fmaf(x[t][q], x[t][q], ss);
        #pragma unroll
        for (int o = 16; o; o >>= 1) ss += __shfl_xor_sync(0xffffffffu, ss, o);
        const float inv = __fdividef(1.0f, fmaxf(sqrtf(ss), 1e-12f));
        uint4 o4;
        ((__nv_bfloat162*)&o4)[0] = __floats2bfloat162_rn(x[t][0]*inv, x[t][1]*inv);
        ((__nv_bfloat162*)&o4)[1] = __floats2bfloat162_rn(x[t][2]*inv, x[t][3]*inv);
        ((__nv_bfloat162*)&o4)[2] = __floats2bfloat162_rn(x[t][4]*inv, x[t][5]*inv);
        ((__nv_bfloat162*)&o4)[3] = __floats2bfloat162_rn(x[t][6]*inv, x[t][7]*inv);
        *(uint4*)(dst + (size_t)(i0 + t) * NC + lane * 8) = o4;
    }
}

// ============================================================================
// Kernel B: cost GEMM via mma.sync bf16 (sm_80+ baseline; compiles for sm_103).
// grid (2 M-halves, 64 batches), 256 threads.  Smem: A[128][264] + B[256][264]
// bf16 (padded rows -> conflict-free fragment LDS).  Warp w: rows 16w..16w+15,
// two 128-col halves of 16 n-tiles each.  Epilogue K' = exp2((dot-1)*K2C+26).
// ============================================================================
#define SPAD 264                       // padded row stride (bf16 elems)
#define COST_SMEM ((128 + 256) * SPAD * 2)

__device__ __forceinline__ void mma16816(float* c, uint32_t a0, uint32_t a1,
                                         uint32_t a2, uint32_t a3,
                                         uint32_t b0, uint32_t b1) {
    asm volatile(
        "mma.sync.aligned.m16n8k16.row.col.f32.bf16.bf16.f32 "
        "{%0,%1,%2,%3}, {%4,%5,%6,%7}, {%8,%9}, {%0,%1,%2,%3};"
        : "+f"(c[0]), "+f"(c[1]), "+f"(c[2]), "+f"(c[3])
        : "r"(a0), "r"(a1), "r"(a2), "r"(a3), "r"(b0), "r"(b1));
}

__global__ __launch_bounds__(256, 1) void cost_kernel()
{
    extern __shared__ char smem[];
    __nv_bfloat16* As = (__nv_bfloat16*)smem;                       // [128][264]
    __nv_bfloat16* Bs = (__nv_bfloat16*)(smem + 128 * SPAD * 2);    // [256][264]

    const int mh = blockIdx.x;     // M half
    const int b  = blockIdx.y;
    const int tid = threadIdx.x, w = tid >> 5, lane = tid & 31;

    // ---- load tiles (uint4 = 8 bf16; SPAD*2 = 528 B, 16B-aligned)
    const uint4* __restrict__ Ag =
        (const uint4*)(g_tok + ((size_t)b * NT + (size_t)mh * 128) * NC);
    #pragma unroll
    for (int it = 0; it < 16; ++it) {
        const int idx = tid + it * 256;
        *(uint4*)(As + (idx >> 5) * SPAD + (idx & 31) * 8) = Ag[idx];
    }
    const uint4* __restrict__ Bg = (const uint4*)(g_tok + ((size_t)(NB + b)) * NT * NC);
    #pragma unroll
    for (int it = 0; it < 32; ++it) {
        const int idx = tid + it * 256;
        *(uint4*)(Bs + (idx >> 5) * SPAD + (idx & 31) * 8) = Bg[idx];
    }
    __syncthreads();

    const int r0 = w * 16;
    const int lr = lane >> 2;          // 0..7
    const int lj = lane & 3;           // 0..3

    const __nv_bfloat16* A0 = As + (r0 + lr) * SPAD + lj * 2;
    const __nv_bfloat16* A8 = A0 + 8 * SPAD;
    const __nv_bfloat16* B0 = Bs + lr * SPAD + lj * 2;   // + n-tile*8 rows

    // output base pointers
    __half* __restrict__ K0 = g_K + ((size_t)b * NT + (size_t)(mh * 128 + r0 + lr)) * NT;
    __half* __restrict__ K8 = K0 + 8 * NT;

    #pragma unroll
    for (int h = 0; h < 2; ++h) {
        float c[16][4];
        #pragma unroll
        for (int nt = 0; nt < 16; ++nt)
            c[nt][0] = c[nt][1] = c[nt][2] = c[nt][3] = 0.0f;

        #pragma unroll
        for (int kc = 0; kc < 16; ++kc) {
            const int ko = kc * 16;
            const uint32_t a0 = *(const uint32_t*)(A0 + ko);
            const uint32_t a1 = *(const uint32_t*)(A8 + ko);
            const uint32_t a2 = *(const uint32_t*)(A0 + ko + 8);
            const uint32_t a3 = *(const uint32_t*)(A8 + ko + 8);
            #pragma unroll
            for (int nt = 0; nt < 16; ++nt) {
                const __nv_bfloat16* bp = B0 + (h * 128 + nt * 8) * SPAD + ko;
                const uint32_t b0 = *(const uint32_t*)bp;
                const uint32_t b1 = *(const uint32_t*)(bp + 8);
                mma16816(c[nt], a0, a1, a2, a3, b0, b1);
            }
        }

        // ---- epilogue: K' = exp2((dot-1)*K2C + SHIFT) -> fp16
        #pragma unroll
        for (int nt = 0; nt < 16; ++nt) {
            const int col = h * 128 + nt * 8 + lj * 2;
            *(__half2*)(K0 + col) = __halves2half2(
                __float2half_rn(exp2f(fmaf(c[nt][0] - 1.0f, K2C, SHIFTF))),
                __float2half_rn(exp2f(fmaf(c[nt][1] - 1.0f, K2C, SHIFTF))));
            *(__half2*)(K8 + col) = __halves2half2(
                __float2half_rn(exp2f(fmaf(c[nt][2] - 1.0f, K2C, SHIFTF))),
                __float2half_rn(exp2f(fmaf(c[nt][3] - 1.0f, K2C, SHIFTF))));
        }
    }
}

// ============================================================================
// Kernel C: linear-domain Sinkhorn, HFMA2 math, fused final mean.
// 1 CTA/batch, 1024 threads, K' fp16 in smem.  uh scaled by 64 (fp16 range).
// ============================================================================
#define SINK_SMEM 150656

__global__ __launch_bounds__(1024, 1) void sinkhorn_kernel(float* __restrict__ out)
{
    extern __shared__ unsigned char sm[];
    __half* Ks  = (__half*)sm;                       // 131072
    float*  prt = (float*)(sm + 131072);             // 16384
    float*  u   = (float*)(sm + 147456);             // 1024
    float*  v   = (float*)(sm + 148480);             // 1024
    __half* uh  = (__half*)(sm + 149504);            // 512  (scaled x64)
    __half* vh  = (__half*)(sm + 150016);            // 512  (unscaled)
    float*  red = (float*)(sm + 150528);             // 128

    const int b = blockIdx.x, tid = threadIdx.x;
    const int w = tid >> 5, lane = tid & 31;

    {   // load K' (128KB)
        const uint4* gk = (const uint4*)(g_K + (size_t)b * NT * NT);
        uint4* sk = (uint4*)Ks;
        #pragma unroll
        for (int q = 0; q < 8; ++q) sk[tid + q * 1024] = gk[tid + q * 1024];
    }
    if (tid < NT) { v[tid] = 1.0f; vh[tid] = __float2half_rn(1.0f); }
    __syncthreads();

    const int g  = tid >> 6;   // row group (16 rows)
    const int jq = tid & 63;   // column quad

    for (int it = 0; it < NITER; ++it) {
        // ---- u-pass: warp per 8 rows, fp16 MAC (chains of <=2 hfma2), f32 reduce
        const uint4 vv = *(const uint4*)(vh + lane * 8);
        const __half2 hv0 = *(const __half2*)&vv.x;
        const __half2 hv1 = *(const __half2*)&vv.y;
        const __half2 hv2 = *(const __half2*)&vv.z;
        const __half2 hv3 = *(const __half2*)&vv.w;
        #pragma unroll
        for (int r = 0; r < 8; ++r) {
            const int i = w * 8 + r;
            const uint4 kw = *(const uint4*)(Ks + (size_t)i * NT + lane * 8);
            __half2 a0 = __hmul2(*(const __half2*)&kw.x, hv0);
            a0 = __hfma2(*(const __half2*)&kw.y, hv1, a0);
            __half2 a1 = __hmul2(*(const __half2*)&kw.z, hv2);
            a1 = __hfma2(*(const __half2*)&kw.w, hv3, a1);
            const float2 f0 = __half22float2(a0);
            const float2 f1 = __half22float2(a1);
            float s = (f0.x + f0.y) + (f1.x + f1.y);
            #pragma unroll
            for (int o = 16; o; o >>= 1) s += __shfl_xor_sync(0xffffffffu, s, o);
            if (lane == 0) {
                const float uu = __fdividef(MUC, s);
                u[i] = uu; uh[i] = __float2half_rn(uu * 64.0f);
            }
        }
        __syncthreads();

        // ---- v-pass: thread owns 4 cols x 16 rows, fp16 MAC (uh scaled), flush @8
        __half2 acc0 = __float2half2_rn(0.0f), acc1 = acc0;
        float p0 = 0.f, p1 = 0.f, p2 = 0.f, p3 = 0.f;
        #pragma unroll
        for (int r = 0; r < 16; ++r) {
            const int i = g * 16 + r;
            const __half2 ud = __half2half2(uh[i]);
            const uint2 kw = *(const uint2*)(Ks + (size_t)i * NT + jq * 4);
            acc0 = __hfma2(*(const __half2*)&kw.x, ud, acc0);
            acc1 = __hfma2(*(const __half2*)&kw.y, ud, acc1);
            if (r == 7) {
                const float2 fa = __half22float2(acc0), fb = __half22float2(acc1);
                p0 += fa.x; p1 += fa.y; p2 += fb.x; p3 += fb.y;
                acc0 = __float2half2_rn(0.0f); acc1 = acc0;
            }
        }
        {
            const float2 fa = __half22float2(acc0), fb = __half22float2(acc1);
            p0 += fa.x; p1 += fa.y; p2 += fb.x; p3 += fb.y;
        }
        *(float4*)&prt[g * NT + jq * 4] = make_float4(p0, p1, p2, p3);
        __syncthreads();
        if (tid < NT) {
            float s = 0.f;
            #pragma unroll
            for (int gg = 0; gg < 16; ++gg) s += prt[gg * NT + tid];
            const float nv = __fdividef(0.25f, s);   // MUC * 64 (uh scale cancels)
            v[tid] = nv; vh[tid] = __float2half_rn(nv);
        }
        __syncthreads();
    }

    // ---- transport loss (f32): sum u_i K'_ij v_j * cost_ij, cost from log2(K')
    float vl[8];
    {
        const float4 v0 = *(const float4*)&v[lane * 8];
        const float4 v1 = *(const float4*)&v[lane * 8 + 4];
        vl[0]=v0.x; vl[1]=v0.y; vl[2]=v0.z; vl[3]=v0.w;
        vl[4]=v1.x; vl[5]=v1.y; vl[6]=v1.z; vl[7]=v1.w;
    }
    float acc = 0.0f;
    #pragma unroll
    for (int r = 0; r < 8; ++r) {
        const int i = w * 8 + r;
        const float ui = u[i];
        const uint4 kw = *(const uint4*)(Ks + (size_t)i * NT + lane * 8);
        float kf[8];
        {
            float2 f;
            f = __half22float2(*(const __half2*)&kw.x); kf[0]=f.x; kf[1]=f.y;
            f = __half22float2(*(const __half2*)&kw.y); kf[2]=f.x; kf[3]=f.y;
            f = __half22float2(*(const __half2*)&kw.z); kf[4]=f.x; kf[5]=f.y;
            f = __half22float2(*(const __half2*)&kw.w); kf[6]=f.x; kf[7]=f.y;
        }
        #pragma unroll
        for (int q = 0; q < 8; ++q) {
            const float k = kf[q];
            if (k > 0.0f) {
                const float cost = (SHIFTF - __log2f(k)) * INV_K2;  // == 1 - dot
                acc = fmaf(ui * k * vl[q], cost, acc);
            }
        }
    }
    #pragma unroll
    for (int o = 16; o; o >>= 1) acc += __shfl_xor_sync(0xffffffffu, acc, o);
    if (lane == 0) red[w] = acc;
    __syncthreads();
    if (w == 0) {
        float s = red[lane];
        #pragma unroll
        for (int o = 16; o; o >>= 1) s += __shfl_xor_sync(0xffffffffu, s, o);
        if (lane == 0) {
            g_loss[b] = s;
            __threadfence();
            if (atomicAdd(&g_ctr, 1u) == NB - 1) {   // last CTA: deterministic mean
                __threadfence();
                float tot = 0.0f;
                #pragma unroll
                for (int i = 0; i < NB; ++i) tot += __ldcg(&g_loss[i]);
                out[0] = tot * (1.0f / NB);
            }
        }
    }
}

// ============================================================================
extern "C" void kernel_launch(void* const* d_in, const int* in_sizes, int n_in,
                              void* d_out, int out_size)
{
    const float* pred = (const float*)d_in[0];
    const float* tgt  = (const float*)d_in[1];
    float* out = (float*)d_out;

    gather_norm_kernel<<<dim3(NB, 2, 8), 256>>>(pred, tgt);

    cudaFuncSetAttribute(cost_kernel, cudaFuncAttributeMaxDynamicSharedMemorySize, COST_SMEM);
    cost_kernel<<<dim3(2, NB), 256, COST_SMEM>>>();

    cudaFuncSetAttribute(sinkhorn_kernel, cudaFuncAttributeMaxDynamicSharedMemorySize, SINK_SMEM);
    sinkhorn_kernel<<<NB, 1024, SINK_SMEM>>>(out);
}

// round 5
// speedup vs baseline: 1.2478x; 1.0811x over previous
#include <cuda_runtime.h>
#include <cuda_fp16.h>
#include <cuda_bf16.h>
#include <cstdint>

// ---------------- problem constants ----------------
#define NB   64
#define NT   256
#define NC   256
#define HW   4096
#define NITER 30

#define K2C     28.853900817779268f   // log2(e)/eps
#define INV_K2  0.03465735902799727f  // eps*ln2
#define SHIFTF  26.0f
#define MUC     (1.0f/256.0f)

// ---------------- scratch ----------------
__device__ __align__(16) __nv_bfloat16 g_samp[(size_t)2 * NB * NC * NT]; // [z][b][c][i] raw samples
__device__ __align__(16) __nv_bfloat16 g_tok[(size_t)2 * NB * NT * NC];  // [z][b][i][c] normalized
__device__ __align__(16) __half        g_K[(size_t)NB * NT * NT];
__device__ float    g_part[2 * NB];
__device__ unsigned g_ctr;

__device__ __forceinline__ uint32_t smem_u32(const void* p) {
    uint32_t a;
    asm("{ .reg .u64 t; cvta.to.shared.u64 t, %1; cvt.u32.u64 %0, t; }" : "=r"(a) : "l"(p));
    return a;
}

// ============================================================================
// Kernel 1: fully-coalesced streaming sampler.
// grid (64, 2, 64): CTA = (batch, tensor, 4-channel group), 256 threads.
// Each float4 slot [4p,4p+4) holds at most one linspace sample (spacing ~16).
// ============================================================================
__global__ __launch_bounds__(256) void sample_kernel(
    const float* __restrict__ pred, const float* __restrict__ tgt)
{
    const int b = blockIdx.x, z = blockIdx.y;
    if (threadIdx.x == 0 && (b | z | blockIdx.z) == 0) g_ctr = 0u;

    const int tid = threadIdx.x;
    const float DELTA = 4095.0f / 255.0f;

    #pragma unroll
    for (int q = 0; q < 4; ++q) {
        const int c = blockIdx.z * 4 + q;
        const float4* __restrict__ plane =
            (const float4*)(((z ? tgt : pred)) + ((size_t)b * NC + c) * HW);
        __nv_bfloat16* __restrict__ dst = g_samp + (((size_t)z * NB + b) * NC + c) * NT;

        float4 f[4];
        #pragma unroll
        for (int k = 0; k < 4; ++k) f[k] = plane[tid + k * 256];

        #pragma unroll
        for (int k = 0; k < 4; ++k) {
            const int p4 = (tid + k * 256) * 4;              // window [p4, p4+4)
            const int cand = (int)(__fdividef((float)(p4 + 2), DELTA));
            #pragma unroll
            for (int d = -1; d <= 1; ++d) {
                const int i = cand + d;
                if (i >= 0 && i < 256) {
                    const int s = (int)(__fmul_rn((float)i, DELTA));  // exact ref truncation
                    if (s >= p4 && s < p4 + 4) {
                        const float* fv = (const float*)&f[k];
                        dst[i] = __float2bfloat16(fv[s - p4]);
                    }
                }
            }
        }
    }
}

// ============================================================================
// Kernel 2: per-(z,b) l2-normalize + transpose [c][i] -> [i][c] (bf16).
// 128 CTAs, 1024 threads.  Smem tile with 8-half-block XOR swizzle on (c>>3).
// ============================================================================
#define TSTR 264
#define NTR_SMEM (256 * TSTR * 2 + 4096 + 1024)

__global__ __launch_bounds__(1024, 1) void norm_transpose_kernel()
{
    extern __shared__ unsigned char sm[];
    __half* T   = (__half*)sm;                           // [256 c][264] swizzled
    float*  pss = (float*)(sm + 256 * TSTR * 2);         // [4][256]
    float*  inv = (float*)(sm + 256 * TSTR * 2 + 4096);  // [256]

    const int zb  = blockIdx.x;
    const int tid = threadIdx.x;

    const uint4* __restrict__ src = (const uint4*)(g_samp + (size_t)zb * NC * NT);
    #pragma unroll
    for (int k = 0; k < 8; ++k) {
        const int idx = tid + k * 1024;
        const int c = idx >> 5, ib = idx & 31;
        *(uint4*)(T + c * TSTR + ((ib ^ ((c >> 3) & 7)) << 3)) = src[idx];
    }
    __syncthreads();

    {   // sum of squares per token
        const int i = tid & 255, part = tid >> 8;
        const int ib = i >> 3, io = i & 7;
        float ss = 0.0f;
        #pragma unroll 8
        for (int cc = 0; cc < 64; ++cc) {
            const int c = part * 64 + cc;
            const float x = __bfloat162float(
                ((const __nv_bfloat16*)T)[c * TSTR + ((ib ^ ((c >> 3) & 7)) << 3) + io]);
            ss = fmaf(x, x, ss);
        }
        pss[part * 256 + i] = ss;
    }
    __syncthreads();
    if (tid < 256) {
        const float ss = pss[tid] + pss[256 + tid] + pss[512 + tid] + pss[768 + tid];
        inv[tid] = __fdividef(1.0f, fmaxf(sqrtf(ss), 1e-12f));
    }
    __syncthreads();

    uint4* __restrict__ dst = (uint4*)(g_tok + (size_t)zb * NT * NC);
    #pragma unroll
    for (int k = 0; k < 8; ++k) {
        const int idx = tid + k * 1024;
        const int i = idx >> 5, c0 = (idx & 31) * 8;
        const float sc = inv[i];
        const int ib = i >> 3, io = i & 7;
        union { uint4 u; __nv_bfloat16 h[8]; } o;
        #pragma unroll
        for (int j = 0; j < 8; ++j) {
            const int c = c0 + j;
            const float x = __bfloat162float(
                ((const __nv_bfloat16*)T)[c * TSTR + ((ib ^ ((c >> 3) & 7)) << 3) + io]);
            o.h[j] = __float2bfloat16(x * sc);
        }
        dst[idx] = o.u;
    }
}

// ============================================================================
// Kernel 3: cost GEMM via mma.sync bf16 (unchanged from round 4).
// ============================================================================
#define SPAD 264
#define COST_SMEM ((128 + 256) * SPAD * 2)

__device__ __forceinline__ void mma16816(float* c, uint32_t a0, uint32_t a1,
                                         uint32_t a2, uint32_t a3,
                                         uint32_t b0, uint32_t b1) {
    asm volatile(
        "mma.sync.aligned.m16n8k16.row.col.f32.bf16.bf16.f32 "
        "{%0,%1,%2,%3}, {%4,%5,%6,%7}, {%8,%9}, {%0,%1,%2,%3};"
        : "+f"(c[0]), "+f"(c[1]), "+f"(c[2]), "+f"(c[3])
        : "r"(a0), "r"(a1), "r"(a2), "r"(a3), "r"(b0), "r"(b1));
}

__global__ __launch_bounds__(256, 1) void cost_kernel()
{
    extern __shared__ char smem[];
    __nv_bfloat16* As = (__nv_bfloat16*)smem;
    __nv_bfloat16* Bs = (__nv_bfloat16*)(smem + 128 * SPAD * 2);

    const int mh = blockIdx.x;
    const int b  = blockIdx.y;
    const int tid = threadIdx.x, w = tid >> 5, lane = tid & 31;

    const uint4* __restrict__ Ag =
        (const uint4*)(g_tok + ((size_t)b * NT + (size_t)mh * 128) * NC);
    #pragma unroll
    for (int it = 0; it < 16; ++it) {
        const int idx = tid + it * 256;
        *(uint4*)(As + (idx >> 5) * SPAD + (idx & 31) * 8) = Ag[idx];
    }
    const uint4* __restrict__ Bg = (const uint4*)(g_tok + ((size_t)(NB + b)) * NT * NC);
    #pragma unroll
    for (int it = 0; it < 32; ++it) {
        const int idx = tid + it * 256;
        *(uint4*)(Bs + (idx >> 5) * SPAD + (idx & 31) * 8) = Bg[idx];
    }
    __syncthreads();

    const int r0 = w * 16;
    const int lr = lane >> 2;
    const int lj = lane & 3;

    const __nv_bfloat16* A0 = As + (r0 + lr) * SPAD + lj * 2;
    const __nv_bfloat16* A8 = A0 + 8 * SPAD;
    const __nv_bfloat16* B0 = Bs + lr * SPAD + lj * 2;

    __half* __restrict__ K0 = g_K + ((size_t)b * NT + (size_t)(mh * 128 + r0 + lr)) * NT;
    __half* __restrict__ K8 = K0 + 8 * NT;

    #pragma unroll
    for (int h = 0; h < 2; ++h) {
        float c[16][4];
        #pragma unroll
        for (int nt = 0; nt < 16; ++nt)
            c[nt][0] = c[nt][1] = c[nt][2] = c[nt][3] = 0.0f;

        #pragma unroll
        for (int kc = 0; kc < 16; ++kc) {
            const int ko = kc * 16;
            const uint32_t a0 = *(const uint32_t*)(A0 + ko);
            const uint32_t a1 = *(const uint32_t*)(A8 + ko);
            const uint32_t a2 = *(const uint32_t*)(A0 + ko + 8);
            const uint32_t a3 = *(const uint32_t*)(A8 + ko + 8);
            #pragma unroll
            for (int nt = 0; nt < 16; ++nt) {
                const __nv_bfloat16* bp = B0 + (h * 128 + nt * 8) * SPAD + ko;
                const uint32_t b0 = *(const uint32_t*)bp;
                const uint32_t b1 = *(const uint32_t*)(bp + 8);
                mma16816(c[nt], a0, a1, a2, a3, b0, b1);
            }
        }

        #pragma unroll
        for (int nt = 0; nt < 16; ++nt) {
            const int col = h * 128 + nt * 8 + lj * 2;
            *(__half2*)(K0 + col) = __halves2half2(
                __float2half_rn(exp2f(fmaf(c[nt][0] - 1.0f, K2C, SHIFTF))),
                __float2half_rn(exp2f(fmaf(c[nt][1] - 1.0f, K2C, SHIFTF))));
            *(__half2*)(K8 + col) = __halves2half2(
                __float2half_rn(exp2f(fmaf(c[nt][2] - 1.0f, K2C, SHIFTF))),
                __float2half_rn(exp2f(fmaf(c[nt][3] - 1.0f, K2C, SHIFTF))));
        }
    }
}

// ============================================================================
// Kernel 4: Sinkhorn split across 2-CTA clusters (rows 0-127 / 128-255).
// 128 CTAs x 1024 threads.  One barrier.cluster per iteration; peer column
// sums pulled via mapa + ld.shared::cluster; double-buffered vs WAR.
// ============================================================================
#define SK_SMEM (65536 + 16384 + 2048 + 1024 + 512 + 256 + 512 + 128)

__global__ __launch_bounds__(1024, 1) __cluster_dims__(2, 1, 1)
void sinkhorn_kernel(float* __restrict__ out)
{
    extern __shared__ unsigned char sm[];
    __half* Ks = (__half*)sm;                          // [128][256] 65536
    float*  prt = (float*)(sm + 65536);                // [16][256]  16384
    float*  cs  = (float*)(sm + 81920);                // [2][256]   2048 (own colsums)
    float*  v   = (float*)(sm + 83968);                // [256]      1024
    float*  u   = (float*)(sm + 84992);                // [128]      512
    __half* uh  = (__half*)(sm + 85504);               // [128]      256
    __half* vh  = (__half*)(sm + 85760);               // [256]      512
    float*  red = (float*)(sm + 86272);                // [32]       128

    const int rank = blockIdx.x & 1;
    const int b    = blockIdx.x >> 1;
    const int tid  = threadIdx.x;
    const int w    = tid >> 5, lane = tid & 31;

    uint32_t cs_peer;
    {
        const uint32_t cs_local = smem_u32(cs);
        asm("mapa.shared::cluster.u32 %0, %1, %2;" : "=r"(cs_peer)
            : "r"(cs_local), "r"(rank ^ 1));
    }

    {   // load my 128 rows of K' (64 KB)
        const uint4* gk = (const uint4*)(g_K + ((size_t)b * NT + (size_t)rank * 128) * NT);
        uint4* sk = (uint4*)Ks;
        #pragma unroll
        for (int q = 0; q < 4; ++q) sk[tid + q * 1024] = gk[tid + q * 1024];
    }
    if (tid < NT) { v[tid] = 1.0f; vh[tid] = __float2half_rn(1.0f); }
    __syncthreads();

    const int g  = tid >> 6;   // 0..15 -> 8 local rows each
    const int jq = tid & 63;   // column quad

    for (int it = 0; it < NITER; ++it) {
        // ---- u-pass: warp w -> local rows 4w..4w+3
        const uint4 vv = *(const uint4*)(vh + lane * 8);
        const __half2 hv0 = *(const __half2*)&vv.x;
        const __half2 hv1 = *(const __half2*)&vv.y;
        const __half2 hv2 = *(const __half2*)&vv.z;
        const __half2 hv3 = *(const __half2*)&vv.w;
        #pragma unroll
        for (int r = 0; r < 4; ++r) {
            const int i = w * 4 + r;
            const uint4 kw = *(const uint4*)(Ks + (size_t)i * NT + lane * 8);
            __half2 a0 = __hmul2(*(const __half2*)&kw.x, hv0);
            a0 = __hfma2(*(const __half2*)&kw.y, hv1, a0);
            __half2 a1 = __hmul2(*(const __half2*)&kw.z, hv2);
            a1 = __hfma2(*(const __half2*)&kw.w, hv3, a1);
            const float2 f0 = __half22float2(a0);
            const float2 f1 = __half22float2(a1);
            float s = (f0.x + f0.y) + (f1.x + f1.y);
            #pragma unroll
            for (int o = 16; o; o >>= 1) s += __shfl_xor_sync(0xffffffffu, s, o);
            if (lane == 0) {
                const float uu = __fdividef(MUC, s);
                u[i] = uu; uh[i] = __float2half_rn(uu * 64.0f);
            }
        }
        __syncthreads();

        // ---- v-pass partials: thread owns 4 cols x 8 local rows
        __half2 acc0 = __float2half2_rn(0.0f), acc1 = acc0;
        #pragma unroll
        for (int r = 0; r < 8; ++r) {
            const int i = g * 8 + r;
            const __half2 ud = __half2half2(uh[i]);
            const uint2 kw = *(const uint2*)(Ks + (size_t)i * NT + jq * 4);
            acc0 = __hfma2(*(const __half2*)&kw.x, ud, acc0);
            acc1 = __hfma2(*(const __half2*)&kw.y, ud, acc1);
        }
        {
            const float2 fa = __half22float2(acc0), fb = __half22float2(acc1);
            *(float4*)&prt[g * NT + jq * 4] = make_float4(fa.x, fa.y, fb.x, fb.y);
        }
        __syncthreads();
        const int buf = it & 1;
        if (tid < NT) {
            float s = 0.f;
            #pragma unroll
            for (int gg = 0; gg < 16; ++gg) s += prt[gg * NT + tid];
            cs[buf * NT + tid] = s;     // my half's column sums
        }
        // publish + sync with peer (release/acquire)
        asm volatile("barrier.cluster.arrive.aligned;" ::: "memory");
        asm volatile("barrier.cluster.wait.aligned;" ::: "memory");
        if (tid < NT) {
            float pv;
            asm volatile("ld.shared::cluster.f32 %0, [%1];"
                         : "=f"(pv) : "r"(cs_peer + (uint32_t)((buf * NT + tid) * 4)));
            const float own = cs[buf * NT + tid];
            const float s = rank == 0 ? (own + pv) : (pv + own);   // identical order both CTAs
            const float nv = __fdividef(0.25f, s);                 // MUC*64 (uh scale cancels)
            v[tid] = nv; vh[tid] = __float2half_rn(nv);
        }
        __syncthreads();
    }

    // ---- transport loss over my 128 rows
    float vl[8];
    {
        const float4 v0 = *(const float4*)&v[lane * 8];
        const float4 v1 = *(const float4*)&v[lane * 8 + 4];
        vl[0]=v0.x; vl[1]=v0.y; vl[2]=v0.z; vl[3]=v0.w;
        vl[4]=v1.x; vl[5]=v1.y; vl[6]=v1.z; vl[7]=v1.w;
    }
    float acc = 0.0f;
    #pragma unroll
    for (int r = 0; r < 4; ++r) {
        const int i = w * 4 + r;
        const float ui = u[i];
        const uint4 kw = *(const uint4*)(Ks + (size_t)i * NT + lane * 8);
        float kf[8];
        {
            float2 f;
            f = __half22float2(*(const __half2*)&kw.x); kf[0]=f.x; kf[1]=f.y;
            f = __half22float2(*(const __half2*)&kw.y); kf[2]=f.x; kf[3]=f.y;
            f = __half22float2(*(const __half2*)&kw.z); kf[4]=f.x; kf[5]=f.y;
            f = __half22float2(*(const __half2*)&kw.w); kf[6]=f.x; kf[7]=f.y;
        }
        #pragma unroll
        for (int q = 0; q < 8; ++q) {
            const float k = kf[q];
            if (k > 0.0f) {
                const float cost = (SHIFTF - __log2f(k)) * INV_K2;  // == 1 - dot
                acc = fmaf(ui * k * vl[q], cost, acc);
            }
        }
    }
    #pragma unroll
    for (int o = 16; o; o >>= 1) acc += __shfl_xor_sync(0xffffffffu, acc, o);
    if (lane == 0) red[w] = acc;
    __syncthreads();
    if (w == 0) {
        float s = red[lane];
        #pragma unroll
        for (int o = 16; o; o >>= 1) s += __shfl_xor_sync(0xffffffffu, s, o);
        if (lane == 0) {
            g_part[blockIdx.x] = s;
            __threadfence();
            if (atomicAdd(&g_ctr, 1u) == 2 * NB - 1) {   // last CTA: deterministic mean
                __threadfence();
                float tot = 0.0f;
                #pragma unroll
                for (int i = 0; i < 2 * NB; ++i) tot += __ldcg(&g_part[i]);
                out[0] = tot * (1.0f / NB);
            }
        }
    }
}

// ============================================================================
extern "C" void kernel_launch(void* const* d_in, const int* in_sizes, int n_in,
                              void* d_out, int out_size)
{
    const float* pred = (const float*)d_in[0];
    const float* tgt  = (const float*)d_in[1];
    float* out = (float*)d_out;

    sample_kernel<<<dim3(NB, 2, 64), 256>>>(pred, tgt);

    cudaFuncSetAttribute(norm_transpose_kernel, cudaFuncAttributeMaxDynamicSharedMemorySize, NTR_SMEM);
    norm_transpose_kernel<<<2 * NB, 1024, NTR_SMEM>>>();

    cudaFuncSetAttribute(cost_kernel, cudaFuncAttributeMaxDynamicSharedMemorySize, COST_SMEM);
    cost_kernel<<<dim3(2, NB), 256, COST_SMEM>>>();

    cudaFuncSetAttribute(sinkhorn_kernel, cudaFuncAttributeMaxDynamicSharedMemorySize, SK_SMEM);
    sinkhorn_kernel<<<2 * NB, 1024, SK_SMEM>>>(out);
}

// round 6
// speedup vs baseline: 1.2568x; 1.0073x over previous
#include <cuda_runtime.h>
#include <cuda_fp16.h>
#include <cuda_bf16.h>
#include <cstdint>

// ---------------- problem constants ----------------
#define NB   64
#define NT   256
#define NC   256
#define HW   4096
#define NITER 30

#define K2C     28.853900817779268f   // log2(e)/eps
#define INV_K2  0.03465735902799727f  // eps*ln2
#define SHIFTF  26.0f
#define MUC     (1.0f/256.0f)

// ---------------- scratch ----------------
__device__ __align__(16) __nv_bfloat16 g_samp[(size_t)2 * NB * NC * NT]; // [z][b][c][i] raw samples
__device__ __align__(16) __nv_bfloat16 g_tok[(size_t)2 * NB * NT * NC];  // [z][b][i][c] normalized
__device__ __align__(16) __half        g_K[(size_t)NB * NT * NT];
__device__ float    g_part[2 * NB];
__device__ unsigned g_ctr;

__device__ __forceinline__ uint32_t smem_u32(const void* p) {
    uint32_t a;
    asm("{ .reg .u64 t; cvta.to.shared.u64 t, %1; cvt.u32.u64 %0, t; }" : "=r"(a) : "l"(p));
    return a;
}

// ============================================================================
// Kernel 1: fully-coalesced streaming sampler.
// grid (64, 2, 64): CTA = (batch, tensor, 4-channel group), 256 threads.
// Each float4 slot [4p,4p+4) holds at most one linspace sample (spacing ~16).
// ============================================================================
__global__ __launch_bounds__(256) void sample_kernel(
    const float* __restrict__ pred, const float* __restrict__ tgt)
{
    const int b = blockIdx.x, z = blockIdx.y;
    if (threadIdx.x == 0 && (b | z | blockIdx.z) == 0) g_ctr = 0u;

    const int tid = threadIdx.x;
    const float DELTA = 4095.0f / 255.0f;

    #pragma unroll
    for (int q = 0; q < 4; ++q) {
        const int c = blockIdx.z * 4 + q;
        const float4* __restrict__ plane =
            (const float4*)(((z ? tgt : pred)) + ((size_t)b * NC + c) * HW);
        __nv_bfloat16* __restrict__ dst = g_samp + (((size_t)z * NB + b) * NC + c) * NT;

        float4 f[4];
        #pragma unroll
        for (int k = 0; k < 4; ++k) f[k] = plane[tid + k * 256];

        #pragma unroll
        for (int k = 0; k < 4; ++k) {
            const int p4 = (tid + k * 256) * 4;              // window [p4, p4+4)
            const int cand = (int)(__fdividef((float)(p4 + 2), DELTA));
            #pragma unroll
            for (int d = -1; d <= 1; ++d) {
                const int i = cand + d;
                if (i >= 0 && i < 256) {
                    const int s = (int)(__fmul_rn((float)i, DELTA));  // exact ref truncation
                    if (s >= p4 && s < p4 + 4) {
                        const float* fv = (const float*)&f[k];
                        dst[i] = __float2bfloat16(fv[s - p4]);
                    }
                }
            }
        }
    }
}

// ============================================================================
// Kernel 2: per-(z,b) l2-normalize + transpose [c][i] -> [i][c] (bf16).
// 128 CTAs, 1024 threads.  Smem tile with 8-half-block XOR swizzle on (c>>3).
// ============================================================================
#define TSTR 264
#define NTR_SMEM (256 * TSTR * 2 + 4096 + 1024)

__global__ __launch_bounds__(1024, 1) void norm_transpose_kernel()
{
    extern __shared__ unsigned char sm[];
    __half* T   = (__half*)sm;                           // [256 c][264] swizzled
    float*  pss = (float*)(sm + 256 * TSTR * 2);         // [4][256]
    float*  inv = (float*)(sm + 256 * TSTR * 2 + 4096);  // [256]

    const int zb  = blockIdx.x;
    const int tid = threadIdx.x;

    const uint4* __restrict__ src = (const uint4*)(g_samp + (size_t)zb * NC * NT);
    #pragma unroll
    for (int k = 0; k < 8; ++k) {
        const int idx = tid + k * 1024;
        const int c = idx >> 5, ib = idx & 31;
        *(uint4*)(T + c * TSTR + ((ib ^ ((c >> 3) & 7)) << 3)) = src[idx];
    }
    __syncthreads();

    {   // sum of squares per token
        const int i = tid & 255, part = tid >> 8;
        const int ib = i >> 3, io = i & 7;
        float ss = 0.0f;
        #pragma unroll 8
        for (int cc = 0; cc < 64; ++cc) {
            const int c = part * 64 + cc;
            const float x = __bfloat162float(
                ((const __nv_bfloat16*)T)[c * TSTR + ((ib ^ ((c >> 3) & 7)) << 3) + io]);
            ss = fmaf(x, x, ss);
        }
        pss[part * 256 + i] = ss;
    }
    __syncthreads();
    if (tid < 256) {
        const float ss = pss[tid] + pss[256 + tid] + pss[512 + tid] + pss[768 + tid];
        inv[tid] = __fdividef(1.0f, fmaxf(sqrtf(ss), 1e-12f));
    }
    __syncthreads();

    uint4* __restrict__ dst = (uint4*)(g_tok + (size_t)zb * NT * NC);
    #pragma unroll
    for (int k = 0; k < 8; ++k) {
        const int idx = tid + k * 1024;
        const int i = idx >> 5, c0 = (idx & 31) * 8;
        const float sc = inv[i];
        const int ib = i >> 3, io = i & 7;
        union { uint4 u; __nv_bfloat16 h[8]; } o;
        #pragma unroll
        for (int j = 0; j < 8; ++j) {
            const int c = c0 + j;
            const float x = __bfloat162float(
                ((const __nv_bfloat16*)T)[c * TSTR + ((ib ^ ((c >> 3) & 7)) << 3) + io]);
            o.h[j] = __float2bfloat16(x * sc);
        }
        dst[idx] = o.u;
    }
}

// ============================================================================
// Kernel 3: cost GEMM via mma.sync bf16 (unchanged from round 4).
// ============================================================================
#define SPAD 264
#define COST_SMEM ((128 + 256) * SPAD * 2)

__device__ __forceinline__ void mma16816(float* c, uint32_t a0, uint32_t a1,
                                         uint32_t a2, uint32_t a3,
                                         uint32_t b0, uint32_t b1) {
    asm volatile(
        "mma.sync.aligned.m16n8k16.row.col.f32.bf16.bf16.f32 "
        "{%0,%1,%2,%3}, {%4,%5,%6,%7}, {%8,%9}, {%0,%1,%2,%3};"
        : "+f"(c[0]), "+f"(c[1]), "+f"(c[2]), "+f"(c[3])
        : "r"(a0), "r"(a1), "r"(a2), "r"(a3), "r"(b0), "r"(b1));
}

__global__ __launch_bounds__(256, 1) void cost_kernel()
{
    extern __shared__ char smem[];
    __nv_bfloat16* As = (__nv_bfloat16*)smem;
    __nv_bfloat16* Bs = (__nv_bfloat16*)(smem + 128 * SPAD * 2);

    const int mh = blockIdx.x;
    const int b  = blockIdx.y;
    const int tid = threadIdx.x, w = tid >> 5, lane = tid & 31;

    const uint4* __restrict__ Ag =
        (const uint4*)(g_tok + ((size_t)b * NT + (size_t)mh * 128) * NC);
    #pragma unroll
    for (int it = 0; it < 16; ++it) {
        const int idx = tid + it * 256;
        *(uint4*)(As + (idx >> 5) * SPAD + (idx & 31) * 8) = Ag[idx];
    }
    const uint4* __restrict__ Bg = (const uint4*)(g_tok + ((size_t)(NB + b)) * NT * NC);
    #pragma unroll
    for (int it = 0; it < 32; ++it) {
        const int idx = tid + it * 256;
        *(uint4*)(Bs + (idx >> 5) * SPAD + (idx & 31) * 8) = Bg[idx];
    }
    __syncthreads();

    const int r0 = w * 16;
    const int lr = lane >> 2;
    const int lj = lane & 3;

    const __nv_bfloat16* A0 = As + (r0 + lr) * SPAD + lj * 2;
    const __nv_bfloat16* A8 = A0 + 8 * SPAD;
    const __nv_bfloat16* B0 = Bs + lr * SPAD + lj * 2;

    __half* __restrict__ K0 = g_K + ((size_t)b * NT + (size_t)(mh * 128 + r0 + lr)) * NT;
    __half* __restrict__ K8 = K0 + 8 * NT;

    #pragma unroll
    for (int h = 0; h < 2; ++h) {
        float c[16][4];
        #pragma unroll
        for (int nt = 0; nt < 16; ++nt)
            c[nt][0] = c[nt][1] = c[nt][2] = c[nt][3] = 0.0f;

        #pragma unroll
        for (int kc = 0; kc < 16; ++kc) {
            const int ko = kc * 16;
            const uint32_t a0 = *(const uint32_t*)(A0 + ko);
            const uint32_t a1 = *(const uint32_t*)(A8 + ko);
            const uint32_t a2 = *(const uint32_t*)(A0 + ko + 8);
            const uint32_t a3 = *(const uint32_t*)(A8 + ko + 8);
            #pragma unroll
            for (int nt = 0; nt < 16; ++nt) {
                const __nv_bfloat16* bp = B0 + (h * 128 + nt * 8) * SPAD + ko;
                const uint32_t b0 = *(const uint32_t*)bp;
                const uint32_t b1 = *(const uint32_t*)(bp + 8);
                mma16816(c[nt], a0, a1, a2, a3, b0, b1);
            }
        }

        #pragma unroll
        for (int nt = 0; nt < 16; ++nt) {
            const int col = h * 128 + nt * 8 + lj * 2;
            *(__half2*)(K0 + col) = __halves2half2(
                __float2half_rn(exp2f(fmaf(c[nt][0] - 1.0f, K2C, SHIFTF))),
                __float2half_rn(exp2f(fmaf(c[nt][1] - 1.0f, K2C, SHIFTF))));
            *(__half2*)(K8 + col) = __halves2half2(
                __float2half_rn(exp2f(fmaf(c[nt][2] - 1.0f, K2C, SHIFTF))),
                __float2half_rn(exp2f(fmaf(c[nt][3] - 1.0f, K2C, SHIFTF))));
        }
    }
}

// ============================================================================
// Kernel 4: Sinkhorn split across 2-CTA clusters (rows 0-127 / 128-255).
// 128 CTAs x 1024 threads.  One barrier.cluster per iteration; peer column
// sums pulled via mapa + ld.shared::cluster; double-buffered vs WAR.
// ============================================================================
#define SK_SMEM (65536 + 16384 + 2048 + 1024 + 512 + 256 + 512 + 128)

__global__ __launch_bounds__(1024, 1) __cluster_dims__(2, 1, 1)
void sinkhorn_kernel(float* __restrict__ out)
{
    extern __shared__ unsigned char sm[];
    __half* Ks = (__half*)sm;                          // [128][256] 65536
    float*  prt = (float*)(sm + 65536);                // [16][256]  16384
    float*  cs  = (float*)(sm + 81920);                // [2][256]   2048 (own colsums)
    float*  v   = (float*)(sm + 83968);                // [256]      1024
    float*  u   = (float*)(sm + 84992);                // [128]      512
    __half* uh  = (__half*)(sm + 85504);               // [128]      256
    __half* vh  = (__half*)(sm + 85760);               // [256]      512
    float*  red = (float*)(sm + 86272);                // [32]       128

    const int rank = blockIdx.x & 1;
    const int b    = blockIdx.x >> 1;
    const int tid  = threadIdx.x;
    const int w    = tid >> 5, lane = tid & 31;

    uint32_t cs_peer;
    {
        const uint32_t cs_local = smem_u32(cs);
        asm("mapa.shared::cluster.u32 %0, %1, %2;" : "=r"(cs_peer)
            : "r"(cs_local), "r"(rank ^ 1));
    }

    {   // load my 128 rows of K' (64 KB)
        const uint4* gk = (const uint4*)(g_K + ((size_t)b * NT + (size_t)rank * 128) * NT);
        uint4* sk = (uint4*)Ks;
        #pragma unroll
        for (int q = 0; q < 4; ++q) sk[tid + q * 1024] = gk[tid + q * 1024];
    }
    if (tid < NT) { v[tid] = 1.0f; vh[tid] = __float2half_rn(1.0f); }
    __syncthreads();

    const int g  = tid >> 6;   // 0..15 -> 8 local rows each
    const int jq = tid & 63;   // column quad

    for (int it = 0; it < NITER; ++it) {
        // ---- u-pass: warp w -> local rows 4w..4w+3
        const uint4 vv = *(const uint4*)(vh + lane * 8);
        const __half2 hv0 = *(const __half2*)&vv.x;
        const __half2 hv1 = *(const __half2*)&vv.y;
        const __half2 hv2 = *(const __half2*)&vv.z;
        const __half2 hv3 = *(const __half2*)&vv.w;
        #pragma unroll
        for (int r = 0; r < 4; ++r) {
            const int i = w * 4 + r;
            const uint4 kw = *(const uint4*)(Ks + (size_t)i * NT + lane * 8);
            __half2 a0 = __hmul2(*(const __half2*)&kw.x, hv0);
            a0 = __hfma2(*(const __half2*)&kw.y, hv1, a0);
            __half2 a1 = __hmul2(*(const __half2*)&kw.z, hv2);
            a1 = __hfma2(*(const __half2*)&kw.w, hv3, a1);
            const float2 f0 = __half22float2(a0);
            const float2 f1 = __half22float2(a1);
            float s = (f0.x + f0.y) + (f1.x + f1.y);
            #pragma unroll
            for (int o = 16; o; o >>= 1) s += __shfl_xor_sync(0xffffffffu, s, o);
            if (lane == 0) {
                const float uu = __fdividef(MUC, s);
                u[i] = uu; uh[i] = __float2half_rn(uu * 64.0f);
            }
        }
        __syncthreads();

        // ---- v-pass partials: thread owns 4 cols x 8 local rows
        __half2 acc0 = __float2half2_rn(0.0f), acc1 = acc0;
        #pragma unroll
        for (int r = 0; r < 8; ++r) {
            const int i = g * 8 + r;
            const __half2 ud = __half2half2(uh[i]);
            const uint2 kw = *(const uint2*)(Ks + (size_t)i * NT + jq * 4);
            acc0 = __hfma2(*(const __half2*)&kw.x, ud, acc0);
            acc1 = __hfma2(*(const __half2*)&kw.y, ud, acc1);
        }
        {
            const float2 fa = __half22float2(acc0), fb = __half22float2(acc1);
            *(float4*)&prt[g * NT + jq * 4] = make_float4(fa.x, fa.y, fb.x, fb.y);
        }
        __syncthreads();
        const int buf = it & 1;
        if (tid < NT) {
            float s = 0.f;
            #pragma unroll
            for (int gg = 0; gg < 16; ++gg) s += prt[gg * NT + tid];
            cs[buf * NT + tid] = s;     // my half's column sums
        }
        // publish + sync with peer (release/acquire)
        asm volatile("barrier.cluster.arrive.aligned;" ::: "memory");
        asm volatile("barrier.cluster.wait.aligned;" ::: "memory");
        if (tid < NT) {
            float pv;
            asm volatile("ld.shared::cluster.f32 %0, [%1];"
                         : "=f"(pv) : "r"(cs_peer + (uint32_t)((buf * NT + tid) * 4)));
            const float own = cs[buf * NT + tid];
            const float s = rank == 0 ? (own + pv) : (pv + own);   // identical order both CTAs
            const float nv = __fdividef(0.25f, s);                 // MUC*64 (uh scale cancels)
            v[tid] = nv; vh[tid] = __float2half_rn(nv);
        }
        __syncthreads();
    }

    // ---- transport loss over my 128 rows
    float vl[8];
    {
        const float4 v0 = *(const float4*)&v[lane * 8];
        const float4 v1 = *(const float4*)&v[lane * 8 + 4];
        vl[0]=v0.x; vl[1]=v0.y; vl[2]=v0.z; vl[3]=v0.w;
        vl[4]=v1.x; vl[5]=v1.y; vl[6]=v1.z; vl[7]=v1.w;
    }
    float acc = 0.0f;
    #pragma unroll
    for (int r = 0; r < 4; ++r) {
        const int i = w * 4 + r;
        const float ui = u[i];
        const uint4 kw = *(const uint4*)(Ks + (size_t)i * NT + lane * 8);
        float kf[8];
        {
            float2 f;
            f = __half22float2(*(const __half2*)&kw.x); kf[0]=f.x; kf[1]=f.y;
            f = __half22float2(*(const __half2*)&kw.y); kf[2]=f.x; kf[3]=f.y;
            f = __half22float2(*(const __half2*)&kw.z); kf[4]=f.x; kf[5]=f.y;
            f = __half22float2(*(const __half2*)&kw.w); kf[6]=f.x; kf[7]=f.y;
        }
        #pragma unroll
        for (int q = 0; q < 8; ++q) {
            const float k = kf[q];
            if (k > 0.0f) {
                const float cost = (SHIFTF - __log2f(k)) * INV_K2;  // == 1 - dot
                acc = fmaf(ui * k * vl[q], cost, acc);
            }
        }
    }
    #pragma unroll
    for (int o = 16; o; o >>= 1) acc += __shfl_xor_sync(0xffffffffu, acc, o);
    if (lane == 0) red[w] = acc;
    __syncthreads();
    if (w == 0) {
        float s = red[lane];
        #pragma unroll
        for (int o = 16; o; o >>= 1) s += __shfl_xor_sync(0xffffffffu, s, o);
        if (lane == 0) {
            g_part[blockIdx.x] = s;
            __threadfence();
            if (atomicAdd(&g_ctr, 1u) == 2 * NB - 1) {   // last CTA: deterministic mean
                __threadfence();
                float tot = 0.0f;
                #pragma unroll
                for (int i = 0; i < 2 * NB; ++i) tot += __ldcg(&g_part[i]);
                out[0] = tot * (1.0f / NB);
            }
        }
    }
}

// ============================================================================
extern "C" void kernel_launch(void* const* d_in, const int* in_sizes, int n_in,
                              void* d_out, int out_size)
{
    const float* pred = (const float*)d_in[0];
    const float* tgt  = (const float*)d_in[1];
    float* out = (float*)d_out;

    sample_kernel<<<dim3(NB, 2, 64), 256>>>(pred, tgt);

    cudaFuncSetAttribute(norm_transpose_kernel, cudaFuncAttributeMaxDynamicSharedMemorySize, NTR_SMEM);
    norm_transpose_kernel<<<2 * NB, 1024, NTR_SMEM>>>();

    cudaFuncSetAttribute(cost_kernel, cudaFuncAttributeMaxDynamicSharedMemorySize, COST_SMEM);
    cost_kernel<<<dim3(2, NB), 256, COST_SMEM>>>();

    cudaFuncSetAttribute(sinkhorn_kernel, cudaFuncAttributeMaxDynamicSharedMemorySize, SK_SMEM);
    sinkhorn_kernel<<<2 * NB, 1024, SK_SMEM>>>(out);
}

// round 8
// speedup vs baseline: 1.3924x; 1.1079x over previous
#include <cuda_runtime.h>
#include <cuda_fp16.h>
#include <cuda_bf16.h>
#include <cstdint>

// ---------------- problem constants ----------------
#define NB   64
#define NT   256
#define NC   256
#define HW   4096
#define NITER 30

#define K2C     28.853900817779268f   // log2(e)/eps
#define INV_K2  0.03465735902799727f  // eps*ln2
#define SHIFTF  26.0f
#define MUC     (1.0f/256.0f)

// ---------------- scratch ----------------
__device__ __align__(16) __nv_bfloat16 g_samp[(size_t)2 * NB * NC * NT]; // [z][b][c][i]
__device__ __align__(16) __nv_bfloat16 g_tok[(size_t)2 * NB * NT * NC];  // [z][b][i][c]
__device__ __align__(16) __half        g_K[(size_t)NB * NT * NT];
__device__ float    g_part[2 * NB];
__device__ unsigned g_ctr;

__device__ __forceinline__ uint32_t smem_u32(const void* p) {
    uint32_t a;
    asm("{ .reg .u64 t; cvta.to.shared.u64 t, %1; cvt.u32.u64 %0, t; }" : "=r"(a) : "l"(p));
    return a;
}
__device__ __forceinline__ uint32_t h2_as_u32(__half lo, __half hi) {
    union { __half2 h; uint32_t u; } c;
    c.h = __halves2half2(lo, hi);
    return c.u;
}

// ============================================================================
// Kernel 1: fully-coalesced streaming sampler (ldcs: no-reuse streaming).
// ============================================================================
__global__ __launch_bounds__(256) void sample_kernel(
    const float* __restrict__ pred, const float* __restrict__ tgt)
{
    const int b = blockIdx.x, z = blockIdx.y;
    if (threadIdx.x == 0 && (b | z | blockIdx.z) == 0) g_ctr = 0u;

    const int tid = threadIdx.x;
    const float DELTA = 4095.0f / 255.0f;

    #pragma unroll
    for (int q = 0; q < 4; ++q) {
        const int c = blockIdx.z * 4 + q;
        const float4* __restrict__ plane =
            (const float4*)(((z ? tgt : pred)) + ((size_t)b * NC + c) * HW);
        __nv_bfloat16* __restrict__ dst = g_samp + (((size_t)z * NB + b) * NC + c) * NT;

        float4 f[4];
        #pragma unroll
        for (int k = 0; k < 4; ++k) f[k] = __ldcs(&plane[tid + k * 256]);

        #pragma unroll
        for (int k = 0; k < 4; ++k) {
            const int p4 = (tid + k * 256) * 4;              // window [p4, p4+4)
            const int cand = (int)(__fdividef((float)(p4 + 2), DELTA));
            #pragma unroll
            for (int d = -1; d <= 1; ++d) {
                const int i = cand + d;
                if (i >= 0 && i < 256) {
                    const int s = (int)(__fmul_rn((float)i, DELTA));  // exact ref trunc
                    if (s >= p4 && s < p4 + 4) {
                        const float* fv = (const float*)&f[k];
                        dst[i] = __float2bfloat16(fv[s - p4]);
                    }
                }
            }
        }
    }
}

// ============================================================================
// Kernel 2: per-(z,b) l2-normalize + transpose [c][i] -> [i][c] (bf16).
// ============================================================================
#define TSTR 264
#define NTR_SMEM (256 * TSTR * 2 + 4096 + 1024)

__global__ __launch_bounds__(1024, 1) void norm_transpose_kernel()
{
    extern __shared__ unsigned char sm[];
    __half* T   = (__half*)sm;
    float*  pss = (float*)(sm + 256 * TSTR * 2);
    float*  inv = (float*)(sm + 256 * TSTR * 2 + 4096);

    const int zb  = blockIdx.x;
    const int tid = threadIdx.x;

    const uint4* __restrict__ src = (const uint4*)(g_samp + (size_t)zb * NC * NT);
    #pragma unroll
    for (int k = 0; k < 8; ++k) {
        const int idx = tid + k * 1024;
        const int c = idx >> 5, ib = idx & 31;
        *(uint4*)(T + c * TSTR + ((ib ^ ((c >> 3) & 7)) << 3)) = src[idx];
    }
    __syncthreads();

    {
        const int i = tid & 255, part = tid >> 8;
        const int ib = i >> 3, io = i & 7;
        float ss = 0.0f;
        #pragma unroll 8
        for (int cc = 0; cc < 64; ++cc) {
            const int c = part * 64 + cc;
            const float x = __bfloat162float(
                ((const __nv_bfloat16*)T)[c * TSTR + ((ib ^ ((c >> 3) & 7)) << 3) + io]);
            ss = fmaf(x, x, ss);
        }
        pss[part * 256 + i] = ss;
    }
    __syncthreads();
    if (tid < 256) {
        const float ss = pss[tid] + pss[256 + tid] + pss[512 + tid] + pss[768 + tid];
        inv[tid] = __fdividef(1.0f, fmaxf(sqrtf(ss), 1e-12f));
    }
    __syncthreads();

    uint4* __restrict__ dst = (uint4*)(g_tok + (size_t)zb * NT * NC);
    #pragma unroll
    for (int k = 0; k < 8; ++k) {
        const int idx = tid + k * 1024;
        const int i = idx >> 5, c0 = (idx & 31) * 8;
        const float sc = inv[i];
        const int ib = i >> 3, io = i & 7;
        union { uint4 u; __nv_bfloat16 h[8]; } o;
        #pragma unroll
        for (int j = 0; j < 8; ++j) {
            const int c = c0 + j;
            const float x = __bfloat162float(
                ((const __nv_bfloat16*)T)[c * TSTR + ((ib ^ ((c >> 3) & 7)) << 3) + io]);
            o.h[j] = __float2bfloat16(x * sc);
        }
        dst[idx] = o.u;
    }
}

// ============================================================================
// Kernel 3: cost GEMM via mma.sync bf16 (unchanged).
// ============================================================================
#define SPAD 264
#define COST_SMEM ((128 + 256) * SPAD * 2)

__device__ __forceinline__ void mma16816bf(float* c, uint32_t a0, uint32_t a1,
                                           uint32_t a2, uint32_t a3,
                                           uint32_t b0, uint32_t b1) {
    asm volatile(
        "mma.sync.aligned.m16n8k16.row.col.f32.bf16.bf16.f32 "
        "{%0,%1,%2,%3}, {%4,%5,%6,%7}, {%8,%9}, {%0,%1,%2,%3};"
        : "+f"(c[0]), "+f"(c[1]), "+f"(c[2]), "+f"(c[3])
        : "r"(a0), "r"(a1), "r"(a2), "r"(a3), "r"(b0), "r"(b1));
}

__global__ __launch_bounds__(256, 1) void cost_kernel()
{
    extern __shared__ char smem[];
    __nv_bfloat16* As = (__nv_bfloat16*)smem;
    __nv_bfloat16* Bs = (__nv_bfloat16*)(smem + 128 * SPAD * 2);

    const int mh = blockIdx.x;
    const int b  = blockIdx.y;
    const int tid = threadIdx.x, w = tid >> 5, lane = tid & 31;

    const uint4* __restrict__ Ag =
        (const uint4*)(g_tok + ((size_t)b * NT + (size_t)mh * 128) * NC);
    #pragma unroll
    for (int it = 0; it < 16; ++it) {
        const int idx = tid + it * 256;
        *(uint4*)(As + (idx >> 5) * SPAD + (idx & 31) * 8) = Ag[idx];
    }
    const uint4* __restrict__ Bg = (const uint4*)(g_tok + ((size_t)(NB + b)) * NT * NC);
    #pragma unroll
    for (int it = 0; it < 32; ++it) {
        const int idx = tid + it * 256;
        *(uint4*)(Bs + (idx >> 5) * SPAD + (idx & 31) * 8) = Bg[idx];
    }
    __syncthreads();

    const int r0 = w * 16;
    const int lr = lane >> 2;
    const int lj = lane & 3;

    const __nv_bfloat16* A0 = As + (r0 + lr) * SPAD + lj * 2;
    const __nv_bfloat16* A8 = A0 + 8 * SPAD;
    const __nv_bfloat16* B0 = Bs + lr * SPAD + lj * 2;

    __half* __restrict__ K0 = g_K + ((size_t)b * NT + (size_t)(mh * 128 + r0 + lr)) * NT;
    __half* __restrict__ K8 = K0 + 8 * NT;

    #pragma unroll
    for (int h = 0; h < 2; ++h) {
        float c[16][4];
        #pragma unroll
        for (int nt = 0; nt < 16; ++nt)
            c[nt][0] = c[nt][1] = c[nt][2] = c[nt][3] = 0.0f;

        #pragma unroll
        for (int kc = 0; kc < 16; ++kc) {
            const int ko = kc * 16;
            const uint32_t a0 = *(const uint32_t*)(A0 + ko);
            const uint32_t a1 = *(const uint32_t*)(A8 + ko);
            const uint32_t a2 = *(const uint32_t*)(A0 + ko + 8);
            const uint32_t a3 = *(const uint32_t*)(A8 + ko + 8);
            #pragma unroll
            for (int nt = 0; nt < 16; ++nt) {
                const __nv_bfloat16* bp = B0 + (h * 128 + nt * 8) * SPAD + ko;
                mma16816bf(c[nt], a0, a1, a2, a3,
                           *(const uint32_t*)bp, *(const uint32_t*)(bp + 8));
            }
        }

        #pragma unroll
        for (int nt = 0; nt < 16; ++nt) {
            const int col = h * 128 + nt * 8 + lj * 2;
            *(__half2*)(K0 + col) = __halves2half2(
                __float2half_rn(exp2f(fmaf(c[nt][0] - 1.0f, K2C, SHIFTF))),
                __float2half_rn(exp2f(fmaf(c[nt][1] - 1.0f, K2C, SHIFTF))));
            *(__half2*)(K8 + col) = __halves2half2(
                __float2half_rn(exp2f(fmaf(c[nt][2] - 1.0f, K2C, SHIFTF))),
                __float2half_rn(exp2f(fmaf(c[nt][3] - 1.0f, K2C, SHIFTF))));
        }
    }
}

// ============================================================================
// Kernel 4: Sinkhorn, tensor-core matvecs with register-resident K fragments.
// 2-CTA clusters (128 rows each), 512 threads (16 warps), f32 accumulators.
//   u-pass: C = K * [v v ... v]   (B cols identical -> lane accum = rowsum)
//   v-pass: C = [u;u;...;u] * K   (A rows identical -> lane accum = colsum)
// K fragments preloaded once into registers; loop does NO K smem traffic.
// ============================================================================
#define SK_KS    0
#define SK_PSUM  65536            // [2][128] f32
#define SK_CS    (65536+1024)     // [2][256] f32
#define SK_V     (65536+1024+2048)
#define SK_U     (SK_V+1024)
#define SK_UH    (SK_U+512)
#define SK_VH    (SK_UH+256)
#define SK_RED   (SK_VH+512)
#define SK_SMEM  (SK_RED+128)

__device__ __forceinline__ void mma16816f(float* c, uint32_t a0, uint32_t a1,
                                          uint32_t a2, uint32_t a3,
                                          uint32_t b0, uint32_t b1) {
    asm volatile(
        "mma.sync.aligned.m16n8k16.row.col.f32.f16.f16.f32 "
        "{%0,%1,%2,%3}, {%4,%5,%6,%7}, {%8,%9}, {%0,%1,%2,%3};"
        : "+f"(c[0]), "+f"(c[1]), "+f"(c[2]), "+f"(c[3])
        : "r"(a0), "r"(a1), "r"(a2), "r"(a3), "r"(b0), "r"(b1));
}

__global__ __launch_bounds__(512, 1) __cluster_dims__(2, 1, 1)
void sinkhorn_kernel(float* __restrict__ out)
{
    extern __shared__ unsigned char sm[];
    __half* Ks   = (__half*)(sm + SK_KS);      // [128][256] local rows
    float*  psum = (float*)(sm + SK_PSUM);
    float*  cs   = (float*)(sm + SK_CS);
    float*  v    = (float*)(sm + SK_V);
    float*  u    = (float*)(sm + SK_U);
    __half* uh   = (__half*)(sm + SK_UH);
    __half* vh   = (__half*)(sm + SK_VH);
    float*  red  = (float*)(sm + SK_RED);

    const int rank = blockIdx.x & 1;
    const int b    = blockIdx.x >> 1;
    const int tid  = threadIdx.x;
    const int w    = tid >> 5, lane = tid & 31;
    const int lr4  = lane >> 2, lj = lane & 3;

    uint32_t cs_peer;
    {
        const uint32_t cs_local = smem_u32(cs);
        asm("mapa.shared::cluster.u32 %0, %1, %2;" : "=r"(cs_peer)
            : "r"(cs_local), "r"(rank ^ 1));
    }

    {   // load my 128 rows of K' (64 KB)
        const uint4* gk = (const uint4*)(g_K + ((size_t)b * NT + (size_t)rank * 128) * NT);
        uint4* sk = (uint4*)Ks;
        #pragma unroll
        for (int q = 0; q < 8; ++q) sk[tid + q * 512] = gk[tid + q * 512];
    }
    if (tid < NT) { v[tid] = 1.0f; vh[tid] = __float2half_rn(1.0f); }
    __syncthreads();

    // ---- preload register fragments (once) ----
    // u-pass A frags: warp w -> rowtile rt = w&7 (rows rt*16..+15), khalf kh = w>>3
    const int rt = w & 7, kh = w >> 3;
    uint32_t afr[8][4];
    #pragma unroll
    for (int t = 0; t < 8; ++t) {
        const int kt = (kh * 8 + t) * 16 + 2 * lj;
        afr[t][0] = *(const uint32_t*)&Ks[(rt * 16 + lr4) * NT + kt];
        afr[t][1] = *(const uint32_t*)&Ks[(rt * 16 + 8 + lr4) * NT + kt];
        afr[t][2] = *(const uint32_t*)&Ks[(rt * 16 + lr4) * NT + kt + 8];
        afr[t][3] = *(const uint32_t*)&Ks[(rt * 16 + 8 + lr4) * NT + kt + 8];
    }
    // v-pass B frags: warp w -> ntiles 2w, 2w+1 (8 cols each); k = 128 local rows
    uint32_t bfr[2][8][2];
    #pragma unroll
    for (int n2 = 0; n2 < 2; ++n2) {
        const int col = (2 * w + n2) * 8 + lr4;
        #pragma unroll
        for (int t = 0; t < 8; ++t) {
            const int k0 = t * 16 + 2 * lj;
            bfr[n2][t][0] = h2_as_u32(Ks[(size_t)k0 * NT + col],
                                      Ks[(size_t)(k0 + 1) * NT + col]);
            bfr[n2][t][1] = h2_as_u32(Ks[(size_t)(k0 + 8) * NT + col],
                                      Ks[(size_t)(k0 + 9) * NT + col]);
        }
    }

    for (int it = 0; it < NITER; ++it) {
        // ---- u-pass: rowsum partials over kh's 128 columns
        {
            float c[4] = {0.f, 0.f, 0.f, 0.f};
            #pragma unroll
            for (int t = 0; t < 8; ++t) {
                const int kt = (kh * 8 + t) * 16 + 2 * lj;
                const uint32_t b0 = *(const uint32_t*)&vh[kt];
                const uint32_t b1 = *(const uint32_t*)&vh[kt + 8];
                mma16816f(c, afr[t][0], afr[t][1], afr[t][2], afr[t][3], b0, b1);
            }
            if (lj == 0) {
                psum[kh * 128 + rt * 16 + lr4]     = c[0];
                psum[kh * 128 + rt * 16 + 8 + lr4] = c[2];
            }
        }
        __syncthreads();
        if (tid < 128) {
            const float s = psum[tid] + psum[128 + tid];
            const float uu = __fdividef(MUC, s);
            u[tid] = uu; uh[tid] = __float2half_rn(uu * 64.0f);
        }
        __syncthreads();

        // ---- v-pass: colsum partials over my 128 rows
        const int buf = it & 1;
        #pragma unroll
        for (int n2 = 0; n2 < 2; ++n2) {
            float c[4] = {0.f, 0.f, 0.f, 0.f};
            #pragma unroll
            for (int t = 0; t < 8; ++t) {
                const int k0 = t * 16 + 2 * lj;
                const uint32_t a0 = *(const uint32_t*)&uh[k0];
                const uint32_t a2 = *(const uint32_t*)&uh[k0 + 8];
                mma16816f(c, a0, a0, a2, a2, bfr[n2][t][0], bfr[n2][t][1]);
            }
            if (lane < 4) {
                cs[buf * NT + (2 * w + n2) * 8 + 2 * lane]     = c[0];
                cs[buf * NT + (2 * w + n2) * 8 + 2 * lane + 1] = c[1];
            }
        }
        // cluster-wide barrier (release/acquire): cs published both sides
        asm volatile("barrier.cluster.arrive.aligned;" ::: "memory");
        asm volatile("barrier.cluster.wait.aligned;" ::: "memory");
        if (tid < NT) {
            float pv;
            asm volatile("ld.shared::cluster.f32 %0, [%1];"
                         : "=f"(pv) : "r"(cs_peer + (uint32_t)((buf * NT + tid) * 4)));
            const float own = cs[buf * NT + tid];
            const float s = rank == 0 ? (own + pv) : (pv + own);   // same order both CTAs
            const float nv = __fdividef(0.25f, s);                 // MUC*64 (uh scale cancels)
            v[tid] = nv; vh[tid] = __float2half_rn(nv);
        }
        __syncthreads();
    }

    // ---- transport loss over my 128 rows (warp w -> rows 8w..8w+7)
    float vl[8];
    {
        const float4 v0 = *(const float4*)&v[lane * 8];
        const float4 v1 = *(const float4*)&v[lane * 8 + 4];
        vl[0]=v0.x; vl[1]=v0.y; vl[2]=v0.z; vl[3]=v0.w;
        vl[4]=v1.x; vl[5]=v1.y; vl[6]=v1.z; vl[7]=v1.w;
    }
    float acc = 0.0f;
    #pragma unroll
    for (int r = 0; r < 8; ++r) {
        const int i = w * 8 + r;
        const float ui = u[i];
        const uint4 kw = *(const uint4*)(Ks + (size_t)i * NT + lane * 8);
        float kf[8];
        {
            float2 f;
            f = __half22float2(*(const __half2*)&kw.x); kf[0]=f.x; kf[1]=f.y;
            f = __half22float2(*(const __half2*)&kw.y); kf[2]=f.x; kf[3]=f.y;
            f = __half22float2(*(const __half2*)&kw.z); kf[4]=f.x; kf[5]=f.y;
            f = __half22float2(*(const __half2*)&kw.w); kf[6]=f.x; kf[7]=f.y;
        }
        #pragma unroll
        for (int q = 0; q < 8; ++q) {
            const float k = kf[q];
            if (k > 0.0f) {
                const float cost = (SHIFTF - __log2f(k)) * INV_K2;  // == 1 - dot
                acc = fmaf(ui * k * vl[q], cost, acc);
            }
        }
    }
    #pragma unroll
    for (int o = 16; o; o >>= 1) acc += __shfl_xor_sync(0xffffffffu, acc, o);
    if (lane == 0) red[w] = acc;
    __syncthreads();
    if (w == 0) {
        float s = (lane < 16) ? red[lane] : 0.0f;
        #pragma unroll
        for (int o = 16; o; o >>= 1) s += __shfl_xor_sync(0xffffffffu, s, o);
        if (lane == 0) {
            g_part[blockIdx.x] = s;
            __threadfence();
            if (atomicAdd(&g_ctr, 1u) == 2 * NB - 1) {   // last CTA: deterministic mean
                __threadfence();
                float tot = 0.0f;
                #pragma unroll
                for (int i = 0; i < 2 * NB; ++i) tot += __ldcg(&g_part[i]);
                out[0] = tot * (1.0f / NB);
            }
        }
    }
}

// ============================================================================
extern "C" void kernel_launch(void* const* d_in, const int* in_sizes, int n_in,
                              void* d_out, int out_size)
{
    const float* pred = (const float*)d_in[0];
    const float* tgt  = (const float*)d_in[1];
    float* out = (float*)d_out;

    sample_kernel<<<dim3(NB, 2, 64), 256>>>(pred, tgt);

    cudaFuncSetAttribute(norm_transpose_kernel, cudaFuncAttributeMaxDynamicSharedMemorySize, NTR_SMEM);
    norm_transpose_kernel<<<2 * NB, 1024, NTR_SMEM>>>();

    cudaFuncSetAttribute(cost_kernel, cudaFuncAttributeMaxDynamicSharedMemorySize, COST_SMEM);
    cost_kernel<<<dim3(2, NB), 256, COST_SMEM>>>();

    cudaFuncSetAttribute(sinkhorn_kernel, cudaFuncAttributeMaxDynamicSharedMemorySize, SK_SMEM);
    sinkhorn_kernel<<<2 * NB, 512, SK_SMEM>>>(out);
}